// round 14
// baseline (speedup 1.0000x reference)
#include <cuda_runtime.h>
#include <cuda_fp16.h>
#include <cstdint>

// Problem constants
#define CDIM   768
#define TSEQ   1024
#define BATCH  8
#define NHEAD  12
#define DHEAD  64
#define MPAD   8
#define QKVN   2304          // 3*C
#define NTOK   8192          // B*T

// Scratch (allocation-free: device globals)
__device__ unsigned char g_mask[NTOK];                 // canonical mask
__device__ int    g_gidx[NTOK];                        // compact idx -> token idx
__device__ int    g_count;                             // # unmasked tokens (global)
__device__ int    g_qcnt[BATCH];                       // per-batch unmasked count
__device__ int    g_qpre[BATCH];                       // per-batch compact prefix
__device__ __half g_qkvh[(size_t)(NTOK + 1) * QKVN];   // fp16 qkv COMPACT rows; row NTOK = zero row
__device__ __half g_F16[(size_t)NTOK * CDIM];          // feats fp16 COMPACT rows
__device__ __half g_W16[(size_t)QKVN * CDIM];          // Wqkv fp16
__device__ __half g_P16[(size_t)CDIM * CDIM];          // Wp fp16
__device__ __half g_O16[(size_t)NTOK * CDIM];          // attention O fp16 COMPACT rows

__device__ __forceinline__ uint32_t smem_u32(const void* p) {
    uint32_t a;
    asm("{ .reg .u64 t; cvta.to.shared.u64 t, %1; cvt.u32.u64 %0, t; }" : "=r"(a) : "l"(p));
    return a;
}
__device__ __forceinline__ void ldsm4(uint32_t addr, uint32_t& r0, uint32_t& r1,
                                      uint32_t& r2, uint32_t& r3) {
    asm volatile("ldmatrix.sync.aligned.m8n8.x4.shared.b16 {%0,%1,%2,%3}, [%4];"
                 : "=r"(r0), "=r"(r1), "=r"(r2), "=r"(r3) : "r"(addr));
}
__device__ __forceinline__ void ldsm4t(uint32_t addr, uint32_t& r0, uint32_t& r1,
                                       uint32_t& r2, uint32_t& r3) {
    asm volatile("ldmatrix.sync.aligned.m8n8.x4.trans.shared.b16 {%0,%1,%2,%3}, [%4];"
                 : "=r"(r0), "=r"(r1), "=r"(r2), "=r"(r3) : "r"(addr));
}
__device__ __forceinline__ void mma_f16(float* c, const uint32_t* a, const uint32_t* b) {
    asm volatile("mma.sync.aligned.m16n8k16.row.col.f32.f16.f16.f32 "
                 "{%0,%1,%2,%3}, {%4,%5,%6,%7}, {%8,%9}, {%0,%1,%2,%3};"
                 : "+f"(c[0]), "+f"(c[1]), "+f"(c[2]), "+f"(c[3])
                 : "r"(a[0]), "r"(a[1]), "r"(a[2]), "r"(a[3]), "r"(b[0]), "r"(b[1]));
}
__device__ __forceinline__ uint32_t packh2(float lo, float hi) {
    __half2 h = __floats2half2_rn(lo, hi);
    return *reinterpret_cast<uint32_t*>(&h);
}

// ---------------------------------------------------------------------------
// Fused prep: mask dtype detect + expand, global gather, per-batch counts and
// prefixes. One block, 256 threads.
// ---------------------------------------------------------------------------
__global__ void prep(const unsigned int* __restrict__ mwp)
{
    __shared__ int is_bytes;
    __shared__ int base[256];
    const int tid = threadIdx.x;
    const int lane = tid & 31, wid = tid >> 5;

    if (tid == 0) is_bytes = 0;
    __syncthreads();
    int flag = 0;
    for (int i = tid; i < 2048; i += 256) {
        unsigned int w = mwp[i];
        if (w > 1u && w != 0x3F800000u) flag = 1;
    }
    if (flag) atomicOr(&is_bytes, 1);
    __syncthreads();
    if (is_bytes) {
        const unsigned char* mb = (const unsigned char*)mwp;
        for (int i = tid; i < NTOK; i += 256) g_mask[i] = mb[i] ? 1 : 0;
    } else {
        for (int i = tid; i < NTOK; i += 256) g_mask[i] = (mwp[i] != 0u) ? 1 : 0;
    }
    __syncthreads();

    int cnt = 0;
    for (int i = tid * 32; i < tid * 32 + 32; i++) cnt += g_mask[i];
    base[tid] = cnt;
    __syncthreads();
    if (tid == 0) {
        int s = 0;
        for (int t = 0; t < 256; t++) { const int c = base[t]; base[t] = s; s += c; }
        g_count = s;
    }
    __syncthreads();
    {
        int off = base[tid];
        for (int i = tid * 32; i < tid * 32 + 32; i++)
            if (g_mask[i]) g_gidx[off++] = i;
    }

    if (wid < BATCH) {
        const int b = wid;
        int c2 = 0;
        for (int i = lane * 32; i < lane * 32 + 32; i++) c2 += g_mask[b * TSEQ + i];
        #pragma unroll
        for (int d = 16; d >= 1; d >>= 1) c2 += __shfl_xor_sync(0xffffffffu, c2, d);
        if (lane == 0) g_qcnt[b] = c2;
    }
    __syncthreads();
    if (tid == 0) {
        int s = 0;
        for (int b = 0; b < BATCH; b++) { g_qpre[b] = s; s += g_qcnt[b]; }
    }
}

// ---------------------------------------------------------------------------
// Fused: gathered feats convert + W/P converts + out-row zeroing + zero row.
// ---------------------------------------------------------------------------
#define CN1 (NTOK * CDIM / 4)
#define CN2 (QKVN * CDIM / 4)
#define CN3 (CDIM * CDIM / 4)
#define CNT (CN1 + CN2 + CN3)
#define ZO_PER_ROW (CDIM / 4)
#define ZO_TOTAL   ((MPAD + NTOK) * ZO_PER_ROW)
#define ZP_TOTAL   (2 * CDIM * 2 / 16)

__global__ void pre_cz(const float* __restrict__ feats,
                       const float* __restrict__ Wqkv,
                       const float* __restrict__ Wp,
                       float* __restrict__ out)
{
    const int i = blockIdx.x * blockDim.x + threadIdx.x;
    if (i < CN1) {
        const int r = i / (CDIM / 4);
        if (r >= g_count) return;
        const int j = i % (CDIM / 4);
        const int tok = g_gidx[r];
        const float4 x = *(const float4*)(feats + (size_t)tok * CDIM + j * 4);
        __half2* dp = (__half2*)(g_F16 + (size_t)r * CDIM + j * 4);
        dp[0] = __floats2half2_rn(x.x, x.y);
        dp[1] = __floats2half2_rn(x.z, x.w);
        return;
    }
    if (i < CNT) {
        const float* src; __half* dst; int j;
        if (i < CN1 + CN2) { src = Wqkv; dst = g_W16; j = i - CN1; }
        else               { src = Wp;   dst = g_P16; j = i - CN1 - CN2; }
        const float4 x = *(const float4*)(src + (size_t)j * 4);
        __half2* dp = (__half2*)(dst + (size_t)j * 4);
        dp[0] = __floats2half2_rn(x.x, x.y);
        dp[1] = __floats2half2_rn(x.z, x.w);
        return;
    }
    const int k = i - CNT;
    if (k < ZO_TOTAL) {
        const int row = k / ZO_PER_ROW;
        if (row >= MPAD && g_mask[row - MPAD]) return;
        ((float4*)out)[k] = make_float4(0.f, 0.f, 0.f, 0.f);
        return;
    }
    const int p = k - ZO_TOTAL;
    if (p < ZP_TOTAL)
        ((uint4*)(g_qkvh + (size_t)NTOK * QKVN + CDIM))[p] = make_uint4(0, 0, 0, 0);
}

// ---------------------------------------------------------------------------
// HMMA GEMM over COMPACT rows, 3-stage cp.async pipeline.
// MODE 1: QKV (fp16 compact out, q*0.125*log2e). MODE 0: out-proj (scatter+bias).
// ---------------------------------------------------------------------------
#define GK      CDIM
#define NITER   12
#define TSTRIDE 144
#define TILEB   (128 * TSTRIDE)
#define GSTAGES 3
#define GEMM_SMEM (GSTAGES * 2 * TILEB)   // 110592

__device__ __forceinline__ void load_tile(uint32_t sT, const __half* __restrict__ S,
                                          int r0, int kin, int tid)
{
    #pragma unroll
    for (int p = 0; p < 4; p++) {
        const int c = tid + p * 256;
        const int row = c >> 3, cg = c & 7;
        const void* g = S + (size_t)(r0 + row) * GK + kin + cg * 8;
        asm volatile("cp.async.cg.shared.global [%0], [%1], 16;"
                     :: "r"(sT + (uint32_t)(row * TSTRIDE + cg * 16)), "l"(g));
    }
}

template<int MODE>
__global__ void __launch_bounds__(256, 2) mma_gemm(
    const __half* __restrict__ A, const __half* __restrict__ B,
    float* __restrict__ Cmat, const float* __restrict__ bias)
{
    const int row0 = blockIdx.y * 128, col0 = blockIdx.x * 128;
    const int count = g_count;
    if (row0 >= count) return;

    extern __shared__ __align__(128) char smem[];
    const uint32_t sb = smem_u32(smem);
    const int tid = threadIdx.x;
    const int wid = tid >> 5, lane = tid & 31;
    const int wm = wid >> 2, wn = wid & 3;

    uint32_t tA[GSTAGES], tB[GSTAGES];
    #pragma unroll
    for (int s = 0; s < GSTAGES; s++) {
        tA[s] = sb + s * 2 * TILEB;
        tB[s] = tA[s] + TILEB;
    }

    float acc[4][4][4];
    #pragma unroll
    for (int i = 0; i < 4; i++)
        #pragma unroll
        for (int j = 0; j < 4; j++)
            #pragma unroll
            for (int r = 0; r < 4; r++) acc[i][j][r] = 0.f;

    const int mat = lane >> 3, rr = lane & 7;
    const int a_row = wm * 64 + (mat & 1) * 8 + rr;
    const int a_colb = (mat >> 1) * 16;
    const int b_row = wn * 32 + (mat >> 1) * 8 + rr;
    const int b_colb = (mat & 1) * 16;

    // prologue: stages 0 and 1 in flight
    load_tile(tA[0], A, row0, 0, tid);
    load_tile(tB[0], B, col0, 0, tid);
    asm volatile("cp.async.commit_group;" ::: "memory");
    load_tile(tA[1], A, row0, 64, tid);
    load_tile(tB[1], B, col0, 64, tid);
    asm volatile("cp.async.commit_group;" ::: "memory");

    for (int kk = 0; kk < NITER; kk++) {
        const int cur = kk % GSTAGES;
        asm volatile("cp.async.wait_group 1;" ::: "memory");
        __syncthreads();
        if (kk + 2 < NITER) {
            const int nxt = (kk + 2) % GSTAGES;
            load_tile(tA[nxt], A, row0, (kk + 2) * 64, tid);
            load_tile(tB[nxt], B, col0, (kk + 2) * 64, tid);
            asm volatile("cp.async.commit_group;" ::: "memory");
        } else {
            asm volatile("cp.async.commit_group;" ::: "memory");  // empty group keeps wait count aligned
        }
        #pragma unroll
        for (int ks = 0; ks < 4; ks++) {
            uint32_t af[4][4], bf[4][2];
            #pragma unroll
            for (int i = 0; i < 4; i++)
                ldsm4(tA[cur] + (uint32_t)((a_row + i * 16) * TSTRIDE + ks * 32 + a_colb),
                      af[i][0], af[i][1], af[i][2], af[i][3]);
            #pragma unroll
            for (int j2 = 0; j2 < 2; j2++) {
                uint32_t r0, r1, r2, r3;
                ldsm4(tB[cur] + (uint32_t)((b_row + j2 * 16) * TSTRIDE + ks * 32 + b_colb),
                      r0, r1, r2, r3);
                bf[j2*2][0] = r0; bf[j2*2][1] = r1;
                bf[j2*2+1][0] = r2; bf[j2*2+1][1] = r3;
            }
            #pragma unroll
            for (int i = 0; i < 4; i++)
                #pragma unroll
                for (int j = 0; j < 4; j++)
                    mma_f16(acc[i][j], af[i], bf[j]);
        }
    }

    const int gr = lane >> 2, gc = (lane & 3) * 2;
    #pragma unroll
    for (int i = 0; i < 4; i++) {
        const int rAl = row0 + wm * 64 + i * 16 + gr;
        const int rBl = rAl + 8;
        const bool vA = (rAl < count), vB = (rBl < count);
        #pragma unroll
        for (int j = 0; j < 4; j++) {
            const int col = col0 + wn * 32 + j * 8 + gc;
            if (MODE == 0) {
                const float bx = bias[col], by = bias[col + 1];
                if (vA) { const int tok = g_gidx[rAl];
                          float2 w; w.x = acc[i][j][0] + bx; w.y = acc[i][j][1] + by;
                          *(float2*)&Cmat[(size_t)tok * CDIM + col] = w; }
                if (vB) { const int tok = g_gidx[rBl];
                          float2 w; w.x = acc[i][j][2] + bx; w.y = acc[i][j][3] + by;
                          *(float2*)&Cmat[(size_t)tok * CDIM + col] = w; }
            } else {
                const float qs = (col < CDIM) ? (0.125f * 1.44269504f) : 1.f;
                if (vA) *(uint32_t*)&g_qkvh[(size_t)rAl * QKVN + col] =
                            packh2(acc[i][j][0] * qs, acc[i][j][1] * qs);
                if (vB) *(uint32_t*)&g_qkvh[(size_t)rBl * QKVN + col] =
                            packh2(acc[i][j][2] * qs, acc[i][j][3] * qs);
            }
        }
    }
}

// ---------------------------------------------------------------------------
// HMMA flash attention over COMPACT rows, exp2-domain no-max softmax, ones-
// column denominator MMA, 3-stage KV pipeline.
// ---------------------------------------------------------------------------
#define FSTR    72
#define FQBYTES (128 * FSTR * 2)
#define FKVBUF  (64 * FSTR * 2)
#define FSTAGES 3
#define FLASH_SMEM (FQBYTES + FSTAGES * 2 * FKVBUF)   // 73728 + 18432 = 92160... (18432 + 55296)

__device__ __forceinline__ void flash_load_kv(uint32_t sb, int qbase, int hd,
                                              int kt, int buf, int tid, int nk)
{
    const uint32_t base = sb + FQBYTES + buf * (2 * FKVBUF);
    #pragma unroll
    for (int p = 0; p < 2; p++) {
        const int c = tid + p * 256;
        const int row = c >> 3, cg = c & 7;
        const int s = kt * 64 + row;
        const size_t crow = (s < nk) ? (size_t)(qbase + s) : (size_t)NTOK;
        const uint32_t so = (uint32_t)(row * FSTR + cg * 8) * 2;
        const void* sk = g_qkvh + crow * QKVN + CDIM + hd + cg * 8;
        const void* sv = g_qkvh + crow * QKVN + 2 * CDIM + hd + cg * 8;
        asm volatile("cp.async.cg.shared.global [%0], [%1], 16;" :: "r"(base + so), "l"(sk));
        asm volatile("cp.async.cg.shared.global [%0], [%1], 16;" :: "r"(base + FKVBUF + so), "l"(sv));
    }
    asm volatile("cp.async.commit_group;" ::: "memory");
}

__global__ void __launch_bounds__(256, 2) flash_mma()
{
    const int bh = blockIdx.y, b = bh / NHEAD, h = bh % NHEAD;
    const int q0 = blockIdx.x * 128;
    const int qcnt = g_qcnt[b];
    if (q0 >= qcnt) return;

    extern __shared__ __align__(128) char fsm[];
    const uint32_t sb = smem_u32(fsm);
    const int tid = threadIdx.x, lane = tid & 31, wid = tid >> 5;
    const int hd = h * DHEAD;
    const int qbase = g_qpre[b];

    const int nk = qcnt;
    const int ntiles = (nk + 63) >> 6;
    const int nk_pad = ntiles << 6;

    // Q stage (group 0)
    #pragma unroll
    for (int p = 0; p < 4; p++) {
        const int c = tid + p * 256;
        const int row = c >> 3, cg = c & 7;
        int qr = q0 + row; if (qr >= qcnt) qr = qcnt - 1;
        const uint32_t so = sb + (uint32_t)(row * FSTR + cg * 8) * 2;
        const void* src = g_qkvh + (size_t)(qbase + qr) * QKVN + hd + cg * 8;
        asm volatile("cp.async.cg.shared.global [%0], [%1], 16;" :: "r"(so), "l"(src));
    }
    asm volatile("cp.async.commit_group;" ::: "memory");
    // KV stages 0, 1 in flight
    flash_load_kv(sb, qbase, hd, 0, 0, tid, nk);
    if (ntiles > 1) flash_load_kv(sb, qbase, hd, 1, 1, tid, nk);
    else            asm volatile("cp.async.commit_group;" ::: "memory");
    asm volatile("cp.async.wait_group 1;" ::: "memory");   // Q + kv0 done
    __syncthreads();

    uint32_t qf[4][4];
    {
        const int m0 = wid * 16;
        #pragma unroll
        for (int ks = 0; ks < 4; ks++) {
            const uint32_t a = sb + (uint32_t)((m0 + (lane & 15)) * FSTR
                                               + ks * 16 + ((lane >> 4) << 3)) * 2;
            ldsm4(a, qf[ks][0], qf[ks][1], qf[ks][2], qf[ks][3]);
        }
    }

    float of[8][4];
    #pragma unroll
    for (int j = 0; j < 8; j++)
        #pragma unroll
        for (int r = 0; r < 4; r++) of[j][r] = 0.f;
    float ofl[4] = {0.f, 0.f, 0.f, 0.f};
    const uint32_t onesb = (lane < 4) ? 0x3C003C00u : 0u;
    const uint32_t bones[2] = { onesb, onesb };

    for (int kt = 0; kt < ntiles; kt++) {
        const int cur = kt % FSTAGES;
        if (kt > 0) {
            asm volatile("cp.async.wait_group 1;" ::: "memory");
            __syncthreads();
        }
        if (kt + 2 < ntiles)
            flash_load_kv(sb, qbase, hd, kt + 2, (kt + 2) % FSTAGES, tid, nk);
        else
            asm volatile("cp.async.commit_group;" ::: "memory");

        const uint32_t sK = sb + FQBYTES + cur * (2 * FKVBUF);
        const uint32_t sV = sK + FKVBUF;

        float sf[8][4];
        #pragma unroll
        for (int j = 0; j < 8; j++)
            #pragma unroll
            for (int r = 0; r < 4; r++) sf[j][r] = 0.f;
        #pragma unroll
        for (int ks = 0; ks < 4; ks++) {
            uint32_t kf[8][2];
            #pragma unroll
            for (int nf2 = 0; nf2 < 4; nf2++) {
                uint32_t r0, r1, r2, r3;
                const uint32_t a = sK + (uint32_t)((nf2 * 16 + (lane & 7) + ((lane >> 4) << 3)) * FSTR
                                                   + ks * 16 + ((lane >> 3) & 1) * 8) * 2;
                ldsm4(a, r0, r1, r2, r3);
                kf[nf2*2][0] = r0; kf[nf2*2][1] = r1;
                kf[nf2*2+1][0] = r2; kf[nf2*2+1][1] = r3;
            }
            #pragma unroll
            for (int j = 0; j < 8; j++) mma_f16(sf[j], qf[ks], kf[j]);
        }

        uint32_t pf[8], pg[8];
        #pragma unroll
        for (int j = 0; j < 8; j++) {
            __half2 h0 = __floats2half2_rn(sf[j][0], sf[j][1]);
            __half2 h1 = __floats2half2_rn(sf[j][2], sf[j][3]);
            h0 = h2exp2(h0);
            h1 = h2exp2(h1);
            pf[j] = *reinterpret_cast<uint32_t*>(&h0);
            pg[j] = *reinterpret_cast<uint32_t*>(&h1);
        }

        #pragma unroll
        for (int kc = 0; kc < 4; kc++) {
            uint32_t pa[4] = { pf[2*kc], pg[2*kc], pf[2*kc+1], pg[2*kc+1] };
            uint32_t vh[8][2];
            #pragma unroll
            for (int nf2 = 0; nf2 < 4; nf2++) {
                const uint32_t off = (uint32_t)((kc * 16 + (lane & 15)) * FSTR
                                                + nf2 * 16 + ((lane >> 4) << 3)) * 2;
                uint32_t r0, r1, r2, r3;
                ldsm4t(sV + off, r0, r1, r2, r3);
                vh[nf2*2][0] = r0; vh[nf2*2][1] = r1;
                vh[nf2*2+1][0] = r2; vh[nf2*2+1][1] = r3;
            }
            #pragma unroll
            for (int j = 0; j < 8; j++) mma_f16(of[j], pa, vh[j]);
            mma_f16(ofl, pa, bones);
        }
        __syncthreads();   // all warps done with buffer cur before it is reused
    }

    const int leader = lane & ~3;
    const float extra = (float)(TSEQ - nk_pad);
    const float lA = __shfl_sync(0xffffffffu, ofl[0], leader) + extra;
    const float lB = __shfl_sync(0xffffffffu, ofl[2], leader) + extra;
    const float iA = 1.f / lA, iB = 1.f / lB;

    const int rA = q0 + wid * 16 + (lane >> 2);
    const int rB = rA + 8;
    const bool vA = (rA < qcnt), vB = (rB < qcnt);
    const size_t baseA = (size_t)(qbase + (vA ? rA : 0)) * CDIM + hd;
    const size_t baseB = (size_t)(qbase + (vB ? rB : 0)) * CDIM + hd;
    #pragma unroll
    for (int j = 0; j < 8; j++) {
        const int col = j * 8 + (lane & 3) * 2;
        if (vA) *(__half2*)&g_O16[baseA + col] = __floats2half2_rn(of[j][0] * iA, of[j][1] * iA);
        if (vB) *(__half2*)&g_O16[baseB + col] = __floats2half2_rn(of[j][2] * iB, of[j][3] * iB);
    }
}

// ---------------------------------------------------------------------------
extern "C" void kernel_launch(void* const* d_in, const int* in_sizes, int n_in,
                              void* d_out, int out_size)
{
    const float* feats = (const float*)d_in[0];
    const void*  amask = d_in[1];
    const float* Wqkv  = (const float*)d_in[2];
    const float* Wp    = (const float*)d_in[3];
    const float* bp    = (const float*)d_in[4];
    float*       out   = (float*)d_out;

    __half *F16, *W16, *P16, *O16;
    cudaGetSymbolAddress((void**)&F16, g_F16);
    cudaGetSymbolAddress((void**)&W16, g_W16);
    cudaGetSymbolAddress((void**)&P16, g_P16);
    cudaGetSymbolAddress((void**)&O16, g_O16);

    cudaFuncSetAttribute(mma_gemm<0>, cudaFuncAttributeMaxDynamicSharedMemorySize, GEMM_SMEM);
    cudaFuncSetAttribute(mma_gemm<1>, cudaFuncAttributeMaxDynamicSharedMemorySize, GEMM_SMEM);
    cudaFuncSetAttribute(flash_mma, cudaFuncAttributeMaxDynamicSharedMemorySize, FLASH_SMEM);

    // 0) prep + fused convert/zero
    prep<<<1, 256>>>((const unsigned int*)amask);
    pre_cz<<<(CNT + ZO_TOTAL + ZP_TOTAL + 255) / 256, 256>>>(
        feats + (size_t)MPAD * CDIM, Wqkv, Wp, out);

    // 1) QKV projection over compact rows
    mma_gemm<1><<<dim3(QKVN / 128, NTOK / 128), 256, GEMM_SMEM>>>(
        F16, W16, nullptr, nullptr);

    // 2) flash attention over compact rows
    flash_mma<<<dim3(TSEQ / 128, BATCH * NHEAD), 256, FLASH_SMEM>>>();

    // 3) out-proj + bias, compact in, scatter out
    mma_gemm<0><<<dim3(CDIM / 128, NTOK / 128), 256, GEMM_SMEM>>>(
        O16, P16, out + (size_t)MPAD * CDIM, bp);
}

// round 15
// speedup vs baseline: 1.0277x; 1.0277x over previous
#include <cuda_runtime.h>
#include <cuda_fp16.h>
#include <cstdint>

// Problem constants
#define CDIM   768
#define TSEQ   1024
#define BATCH  8
#define NHEAD  12
#define DHEAD  64
#define MPAD   8
#define QKVN   2304          // 3*C
#define NTOK   8192          // B*T

// Scratch (allocation-free: device globals)
__device__ unsigned char g_mask[NTOK];                 // canonical mask
__device__ int    g_gidx[NTOK];                        // compact idx -> token idx
__device__ int    g_count;                             // # unmasked tokens (global)
__device__ int    g_qcnt[BATCH];                       // per-batch unmasked count
__device__ int    g_qpre[BATCH];                       // per-batch compact prefix
__device__ __half g_qkvh[(size_t)(NTOK + 1) * QKVN];   // fp16 qkv COMPACT rows; row NTOK = zero row
__device__ __half g_F16[(size_t)NTOK * CDIM];          // feats fp16 LINEAR token rows
__device__ __half g_W16[(size_t)QKVN * CDIM];          // Wqkv fp16
__device__ __half g_P16[(size_t)CDIM * CDIM];          // Wp fp16
__device__ __half g_O16[(size_t)NTOK * CDIM];          // attention O fp16 COMPACT rows

__device__ __forceinline__ uint32_t smem_u32(const void* p) {
    uint32_t a;
    asm("{ .reg .u64 t; cvta.to.shared.u64 t, %1; cvt.u32.u64 %0, t; }" : "=r"(a) : "l"(p));
    return a;
}
__device__ __forceinline__ void ldsm4(uint32_t addr, uint32_t& r0, uint32_t& r1,
                                      uint32_t& r2, uint32_t& r3) {
    asm volatile("ldmatrix.sync.aligned.m8n8.x4.shared.b16 {%0,%1,%2,%3}, [%4];"
                 : "=r"(r0), "=r"(r1), "=r"(r2), "=r"(r3) : "r"(addr));
}
__device__ __forceinline__ void ldsm4t(uint32_t addr, uint32_t& r0, uint32_t& r1,
                                       uint32_t& r2, uint32_t& r3) {
    asm volatile("ldmatrix.sync.aligned.m8n8.x4.trans.shared.b16 {%0,%1,%2,%3}, [%4];"
                 : "=r"(r0), "=r"(r1), "=r"(r2), "=r"(r3) : "r"(addr));
}
__device__ __forceinline__ void mma_f16(float* c, const uint32_t* a, const uint32_t* b) {
    asm volatile("mma.sync.aligned.m16n8k16.row.col.f32.f16.f16.f32 "
                 "{%0,%1,%2,%3}, {%4,%5,%6,%7}, {%8,%9}, {%0,%1,%2,%3};"
                 : "+f"(c[0]), "+f"(c[1]), "+f"(c[2]), "+f"(c[3])
                 : "r"(a[0]), "r"(a[1]), "r"(a[2]), "r"(a[3]), "r"(b[0]), "r"(b[1]));
}
__device__ __forceinline__ uint32_t packh2(float lo, float hi) {
    __half2 h = __floats2half2_rn(lo, hi);
    return *reinterpret_cast<uint32_t*>(&h);
}

// ---------------------------------------------------------------------------
// Wide prep: block 0 does mask dtype detect + expand + gathers; all other
// blocks convert feats (linear) / Wqkv / Wp to fp16 concurrently.
// ---------------------------------------------------------------------------
#define CN1 (NTOK * CDIM / 4)
#define CN2 (QKVN * CDIM / 4)
#define CN3 (CDIM * CDIM / 4)
#define CNT (CN1 + CN2 + CN3)
#define PREP_GRID (1 + (CNT + 255) / 256)

__global__ void prep(const unsigned int* __restrict__ mwp,
                     const float* __restrict__ feats,
                     const float* __restrict__ Wqkv,
                     const float* __restrict__ Wp)
{
    if (blockIdx.x == 0) {
        __shared__ int is_bytes;
        __shared__ int base[256];
        const int tid = threadIdx.x;
        const int lane = tid & 31, wid = tid >> 5;

        if (tid == 0) is_bytes = 0;
        __syncthreads();
        int flag = 0;
        for (int i = tid; i < 2048; i += 256) {
            unsigned int w = mwp[i];
            if (w > 1u && w != 0x3F800000u) flag = 1;
        }
        if (flag) atomicOr(&is_bytes, 1);
        __syncthreads();
        if (is_bytes) {
            const unsigned char* mb = (const unsigned char*)mwp;
            for (int i = tid; i < NTOK; i += 256) g_mask[i] = mb[i] ? 1 : 0;
        } else {
            for (int i = tid; i < NTOK; i += 256) g_mask[i] = (mwp[i] != 0u) ? 1 : 0;
        }
        __syncthreads();

        int cnt = 0;
        for (int i = tid * 32; i < tid * 32 + 32; i++) cnt += g_mask[i];
        base[tid] = cnt;
        __syncthreads();
        if (tid == 0) {
            int s = 0;
            for (int t = 0; t < 256; t++) { const int c = base[t]; base[t] = s; s += c; }
            g_count = s;
        }
        __syncthreads();
        {
            int off = base[tid];
            for (int i = tid * 32; i < tid * 32 + 32; i++)
                if (g_mask[i]) g_gidx[off++] = i;
        }

        if (wid < BATCH) {
            const int b = wid;
            int c2 = 0;
            for (int i = lane * 32; i < lane * 32 + 32; i++) c2 += g_mask[b * TSEQ + i];
            #pragma unroll
            for (int d = 16; d >= 1; d >>= 1) c2 += __shfl_xor_sync(0xffffffffu, c2, d);
            if (lane == 0) g_qcnt[b] = c2;
        }
        __syncthreads();
        if (tid == 0) {
            int s = 0;
            for (int b = 0; b < BATCH; b++) { g_qpre[b] = s; s += g_qcnt[b]; }
        }
        return;
    }

    // converter blocks (mask-independent)
    const int i = (int)(blockIdx.x - 1) * 256 + threadIdx.x;
    const float* src; __half* dst; int j;
    if (i < CN1)             { src = feats; dst = g_F16; j = i; }
    else if (i < CN1 + CN2)  { src = Wqkv;  dst = g_W16; j = i - CN1; }
    else if (i < CNT)        { src = Wp;    dst = g_P16; j = i - CN1 - CN2; }
    else return;
    const float4 x = *(const float4*)(src + (size_t)j * 4);
    __half2* dp = (__half2*)(dst + (size_t)j * 4);
    dp[0] = __floats2half2_rn(x.x, x.y);
    dp[1] = __floats2half2_rn(x.z, x.w);
}

// ---------------------------------------------------------------------------
// Zero-fill: output rows (head + masked) + K/V cols of the dedicated zero row.
// ---------------------------------------------------------------------------
#define ZO_PER_ROW (CDIM / 4)
#define ZO_TOTAL   ((MPAD + NTOK) * ZO_PER_ROW)
#define ZP_TOTAL   (2 * CDIM * 2 / 16)

__global__ void zero_fill(float* __restrict__ out)
{
    const int i = blockIdx.x * blockDim.x + threadIdx.x;
    if (i < ZO_TOTAL) {
        const int row = i / ZO_PER_ROW;
        if (row >= MPAD && g_mask[row - MPAD]) return;
        ((float4*)out)[i] = make_float4(0.f, 0.f, 0.f, 0.f);
        return;
    }
    const int p = i - ZO_TOTAL;
    if (p < ZP_TOTAL)
        ((uint4*)(g_qkvh + (size_t)NTOK * QKVN + CDIM))[p] = make_uint4(0, 0, 0, 0);
}

// ---------------------------------------------------------------------------
// HMMA GEMM, 2-stage pipeline (proven config). MODE 1: QKV — A gathered from
// linear feats rows via g_gidx, fp16 compact out, q*0.125*log2e. MODE 0:
// out-proj — A linear compact, fp32 scatter + bias.
// ---------------------------------------------------------------------------
#define GK      CDIM
#define NITER   12
#define TSTRIDE 144
#define TILEB   (128 * TSTRIDE)
#define GEMM_SMEM (4 * TILEB)   // 73728

__device__ __forceinline__ void load_tile(uint32_t sT, const __half* __restrict__ S,
                                          int r0, int kin, int tid)
{
    #pragma unroll
    for (int p = 0; p < 4; p++) {
        const int c = tid + p * 256;
        const int row = c >> 3, cg = c & 7;
        const void* g = S + (size_t)(r0 + row) * GK + kin + cg * 8;
        asm volatile("cp.async.cg.shared.global [%0], [%1], 16;"
                     :: "r"(sT + (uint32_t)(row * TSTRIDE + cg * 16)), "l"(g));
    }
}
__device__ __forceinline__ void load_tile_gather(uint32_t sT, const __half* __restrict__ S,
                                                 int r0, int kin, int tid, int count)
{
    #pragma unroll
    for (int p = 0; p < 4; p++) {
        const int c = tid + p * 256;
        const int row = c >> 3, cg = c & 7;
        int gi = r0 + row; if (gi >= count) gi = count - 1;
        const int t = g_gidx[gi];
        const void* g = S + (size_t)t * GK + kin + cg * 8;
        asm volatile("cp.async.cg.shared.global [%0], [%1], 16;"
                     :: "r"(sT + (uint32_t)(row * TSTRIDE + cg * 16)), "l"(g));
    }
}

template<int MODE>
__global__ void __launch_bounds__(256, 2) mma_gemm(
    const __half* __restrict__ A, const __half* __restrict__ B,
    float* __restrict__ Cmat, const float* __restrict__ bias)
{
    const int row0 = blockIdx.y * 128, col0 = blockIdx.x * 128;
    const int count = g_count;
    if (row0 >= count) return;

    extern __shared__ __align__(128) char smem[];
    const uint32_t sb = smem_u32(smem);
    const int tid = threadIdx.x;
    const int wid = tid >> 5, lane = tid & 31;
    const int wm = wid >> 2, wn = wid & 3;

    const uint32_t tA[2] = { sb,         sb + 2 * TILEB };
    const uint32_t tB[2] = { sb + TILEB, sb + 3 * TILEB };

    float acc[4][4][4];
    #pragma unroll
    for (int i = 0; i < 4; i++)
        #pragma unroll
        for (int j = 0; j < 4; j++)
            #pragma unroll
            for (int r = 0; r < 4; r++) acc[i][j][r] = 0.f;

    const int mat = lane >> 3, rr = lane & 7;
    const int a_row = wm * 64 + (mat & 1) * 8 + rr;
    const int a_colb = (mat >> 1) * 16;
    const int b_row = wn * 32 + (mat >> 1) * 8 + rr;
    const int b_colb = (mat & 1) * 16;

    if (MODE == 1) load_tile_gather(tA[0], A, row0, 0, tid, count);
    else           load_tile(tA[0], A, row0, 0, tid);
    load_tile(tB[0], B, col0, 0, tid);
    asm volatile("cp.async.commit_group;" ::: "memory");

    for (int kk = 0; kk < NITER; kk++) {
        const int cur = kk & 1;
        asm volatile("cp.async.wait_group 0;" ::: "memory");
        __syncthreads();
        if (kk + 1 < NITER) {
            if (MODE == 1) load_tile_gather(tA[cur ^ 1], A, row0, (kk + 1) * 64, tid, count);
            else           load_tile(tA[cur ^ 1], A, row0, (kk + 1) * 64, tid);
            load_tile(tB[cur ^ 1], B, col0, (kk + 1) * 64, tid);
            asm volatile("cp.async.commit_group;" ::: "memory");
        }
        #pragma unroll
        for (int ks = 0; ks < 4; ks++) {
            uint32_t af[4][4], bf[4][2];
            #pragma unroll
            for (int i = 0; i < 4; i++)
                ldsm4(tA[cur] + (uint32_t)((a_row + i * 16) * TSTRIDE + ks * 32 + a_colb),
                      af[i][0], af[i][1], af[i][2], af[i][3]);
            #pragma unroll
            for (int j2 = 0; j2 < 2; j2++) {
                uint32_t r0, r1, r2, r3;
                ldsm4(tB[cur] + (uint32_t)((b_row + j2 * 16) * TSTRIDE + ks * 32 + b_colb),
                      r0, r1, r2, r3);
                bf[j2*2][0] = r0; bf[j2*2][1] = r1;
                bf[j2*2+1][0] = r2; bf[j2*2+1][1] = r3;
            }
            #pragma unroll
            for (int i = 0; i < 4; i++)
                #pragma unroll
                for (int j = 0; j < 4; j++)
                    mma_f16(acc[i][j], af[i], bf[j]);
        }
        __syncthreads();
    }

    const int gr = lane >> 2, gc = (lane & 3) * 2;
    #pragma unroll
    for (int i = 0; i < 4; i++) {
        const int rAl = row0 + wm * 64 + i * 16 + gr;
        const int rBl = rAl + 8;
        const bool vA = (rAl < count), vB = (rBl < count);
        #pragma unroll
        for (int j = 0; j < 4; j++) {
            const int col = col0 + wn * 32 + j * 8 + gc;
            if (MODE == 0) {
                const float bx = bias[col], by = bias[col + 1];
                if (vA) { const int tok = g_gidx[rAl];
                          float2 w; w.x = acc[i][j][0] + bx; w.y = acc[i][j][1] + by;
                          *(float2*)&Cmat[(size_t)tok * CDIM + col] = w; }
                if (vB) { const int tok = g_gidx[rBl];
                          float2 w; w.x = acc[i][j][2] + bx; w.y = acc[i][j][3] + by;
                          *(float2*)&Cmat[(size_t)tok * CDIM + col] = w; }
            } else {
                const float qs = (col < CDIM) ? (0.125f * 1.44269504f) : 1.f;
                if (vA) *(uint32_t*)&g_qkvh[(size_t)rAl * QKVN + col] =
                            packh2(acc[i][j][0] * qs, acc[i][j][1] * qs);
                if (vB) *(uint32_t*)&g_qkvh[(size_t)rBl * QKVN + col] =
                            packh2(acc[i][j][2] * qs, acc[i][j][3] * qs);
            }
        }
    }
}

// ---------------------------------------------------------------------------
// HMMA flash attention over COMPACT rows, exp2-domain no-max softmax, ones-
// column denominator MMA, 2-stage KV pipeline (proven config).
// ---------------------------------------------------------------------------
#define FSTR    72
#define FQBYTES (128 * FSTR * 2)
#define FKVBUF  (64 * FSTR * 2)
#define FLASH_SMEM (FQBYTES + 4 * FKVBUF)

__device__ __forceinline__ void flash_load_kv(uint32_t sb, int qbase, int hd,
                                              int kt, int buf, int tid, int nk)
{
    const uint32_t base = sb + FQBYTES + buf * (2 * FKVBUF);
    #pragma unroll
    for (int p = 0; p < 2; p++) {
        const int c = tid + p * 256;
        const int row = c >> 3, cg = c & 7;
        const int s = kt * 64 + row;
        const size_t crow = (s < nk) ? (size_t)(qbase + s) : (size_t)NTOK;
        const uint32_t so = (uint32_t)(row * FSTR + cg * 8) * 2;
        const void* sk = g_qkvh + crow * QKVN + CDIM + hd + cg * 8;
        const void* sv = g_qkvh + crow * QKVN + 2 * CDIM + hd + cg * 8;
        asm volatile("cp.async.cg.shared.global [%0], [%1], 16;" :: "r"(base + so), "l"(sk));
        asm volatile("cp.async.cg.shared.global [%0], [%1], 16;" :: "r"(base + FKVBUF + so), "l"(sv));
    }
    asm volatile("cp.async.commit_group;" ::: "memory");
}

__global__ void __launch_bounds__(256) flash_mma()
{
    const int bh = blockIdx.y, b = bh / NHEAD, h = bh % NHEAD;
    const int q0 = blockIdx.x * 128;
    const int qcnt = g_qcnt[b];
    if (q0 >= qcnt) return;

    extern __shared__ __align__(128) char fsm[];
    const uint32_t sb = smem_u32(fsm);
    const int tid = threadIdx.x, lane = tid & 31, wid = tid >> 5;
    const int hd = h * DHEAD;
    const int qbase = g_qpre[b];

    const int nk = qcnt;
    const int ntiles = (nk + 63) >> 6;
    const int nk_pad = ntiles << 6;

    #pragma unroll
    for (int p = 0; p < 4; p++) {
        const int c = tid + p * 256;
        const int row = c >> 3, cg = c & 7;
        int qr = q0 + row; if (qr >= qcnt) qr = qcnt - 1;
        const uint32_t so = sb + (uint32_t)(row * FSTR + cg * 8) * 2;
        const void* src = g_qkvh + (size_t)(qbase + qr) * QKVN + hd + cg * 8;
        asm volatile("cp.async.cg.shared.global [%0], [%1], 16;" :: "r"(so), "l"(src));
    }
    asm volatile("cp.async.commit_group;" ::: "memory");
    flash_load_kv(sb, qbase, hd, 0, 0, tid, nk);
    asm volatile("cp.async.wait_group 1;" ::: "memory");
    __syncthreads();

    uint32_t qf[4][4];
    {
        const int m0 = wid * 16;
        #pragma unroll
        for (int ks = 0; ks < 4; ks++) {
            const uint32_t a = sb + (uint32_t)((m0 + (lane & 15)) * FSTR
                                               + ks * 16 + ((lane >> 4) << 3)) * 2;
            ldsm4(a, qf[ks][0], qf[ks][1], qf[ks][2], qf[ks][3]);
        }
    }

    float of[8][4];
    #pragma unroll
    for (int j = 0; j < 8; j++)
        #pragma unroll
        for (int r = 0; r < 4; r++) of[j][r] = 0.f;
    float ofl[4] = {0.f, 0.f, 0.f, 0.f};
    const uint32_t onesb = (lane < 4) ? 0x3C003C00u : 0u;
    const uint32_t bones[2] = { onesb, onesb };

    for (int kt = 0; kt < ntiles; kt++) {
        const int cur = kt & 1;
        asm volatile("cp.async.wait_group 0;" ::: "memory");
        __syncthreads();
        if (kt + 1 < ntiles)
            flash_load_kv(sb, qbase, hd, kt + 1, cur ^ 1, tid, nk);

        const uint32_t sK = sb + FQBYTES + cur * (2 * FKVBUF);
        const uint32_t sV = sK + FKVBUF;

        float sf[8][4];
        #pragma unroll
        for (int j = 0; j < 8; j++)
            #pragma unroll
            for (int r = 0; r < 4; r++) sf[j][r] = 0.f;
        #pragma unroll
        for (int ks = 0; ks < 4; ks++) {
            uint32_t kf[8][2];
            #pragma unroll
            for (int nf2 = 0; nf2 < 4; nf2++) {
                uint32_t r0, r1, r2, r3;
                const uint32_t a = sK + (uint32_t)((nf2 * 16 + (lane & 7) + ((lane >> 4) << 3)) * FSTR
                                                   + ks * 16 + ((lane >> 3) & 1) * 8) * 2;
                ldsm4(a, r0, r1, r2, r3);
                kf[nf2*2][0] = r0; kf[nf2*2][1] = r1;
                kf[nf2*2+1][0] = r2; kf[nf2*2+1][1] = r3;
            }
            #pragma unroll
            for (int j = 0; j < 8; j++) mma_f16(sf[j], qf[ks], kf[j]);
        }

        uint32_t pf[8], pg[8];
        #pragma unroll
        for (int j = 0; j < 8; j++) {
            __half2 h0 = __floats2half2_rn(sf[j][0], sf[j][1]);
            __half2 h1 = __floats2half2_rn(sf[j][2], sf[j][3]);
            h0 = h2exp2(h0);
            h1 = h2exp2(h1);
            pf[j] = *reinterpret_cast<uint32_t*>(&h0);
            pg[j] = *reinterpret_cast<uint32_t*>(&h1);
        }

        #pragma unroll
        for (int kc = 0; kc < 4; kc++) {
            uint32_t pa[4] = { pf[2*kc], pg[2*kc], pf[2*kc+1], pg[2*kc+1] };
            uint32_t vh[8][2];
            #pragma unroll
            for (int nf2 = 0; nf2 < 4; nf2++) {
                const uint32_t off = (uint32_t)((kc * 16 + (lane & 15)) * FSTR
                                                + nf2 * 16 + ((lane >> 4) << 3)) * 2;
                uint32_t r0, r1, r2, r3;
                ldsm4t(sV + off, r0, r1, r2, r3);
                vh[nf2*2][0] = r0; vh[nf2*2][1] = r1;
                vh[nf2*2+1][0] = r2; vh[nf2*2+1][1] = r3;
            }
            #pragma unroll
            for (int j = 0; j < 8; j++) mma_f16(of[j], pa, vh[j]);
            mma_f16(ofl, pa, bones);
        }
    }

    const int leader = lane & ~3;
    const float extra = (float)(TSEQ - nk_pad);
    const float lA = __shfl_sync(0xffffffffu, ofl[0], leader) + extra;
    const float lB = __shfl_sync(0xffffffffu, ofl[2], leader) + extra;
    const float iA = 1.f / lA, iB = 1.f / lB;

    const int rA = q0 + wid * 16 + (lane >> 2);
    const int rB = rA + 8;
    const bool vA = (rA < qcnt), vB = (rB < qcnt);
    const size_t baseA = (size_t)(qbase + (vA ? rA : 0)) * CDIM + hd;
    const size_t baseB = (size_t)(qbase + (vB ? rB : 0)) * CDIM + hd;
    #pragma unroll
    for (int j = 0; j < 8; j++) {
        const int col = j * 8 + (lane & 3) * 2;
        if (vA) *(__half2*)&g_O16[baseA + col] = __floats2half2_rn(of[j][0] * iA, of[j][1] * iA);
        if (vB) *(__half2*)&g_O16[baseB + col] = __floats2half2_rn(of[j][2] * iB, of[j][3] * iB);
    }
}

// ---------------------------------------------------------------------------
extern "C" void kernel_launch(void* const* d_in, const int* in_sizes, int n_in,
                              void* d_out, int out_size)
{
    const float* feats = (const float*)d_in[0];
    const void*  amask = d_in[1];
    const float* Wqkv  = (const float*)d_in[2];
    const float* Wp    = (const float*)d_in[3];
    const float* bp    = (const float*)d_in[4];
    float*       out   = (float*)d_out;

    __half *F16, *W16, *P16, *O16;
    cudaGetSymbolAddress((void**)&F16, g_F16);
    cudaGetSymbolAddress((void**)&W16, g_W16);
    cudaGetSymbolAddress((void**)&P16, g_P16);
    cudaGetSymbolAddress((void**)&O16, g_O16);

    cudaFuncSetAttribute(mma_gemm<0>, cudaFuncAttributeMaxDynamicSharedMemorySize, GEMM_SMEM);
    cudaFuncSetAttribute(mma_gemm<1>, cudaFuncAttributeMaxDynamicSharedMemorySize, GEMM_SMEM);
    cudaFuncSetAttribute(flash_mma, cudaFuncAttributeMaxDynamicSharedMemorySize, FLASH_SMEM);

    // 0) wide prep: mask work in block 0, converts in all other blocks
    prep<<<PREP_GRID, 256>>>((const unsigned int*)amask,
                             feats + (size_t)MPAD * CDIM, Wqkv, Wp);
    zero_fill<<<(ZO_TOTAL + ZP_TOTAL + 255) / 256, 256>>>(out);

    // 1) QKV projection: gather linear feats rows -> compact fp16 qkv
    mma_gemm<1><<<dim3(QKVN / 128, NTOK / 128), 256, GEMM_SMEM>>>(
        F16, W16, nullptr, nullptr);

    // 2) flash attention over compact rows
    flash_mma<<<dim3(TSEQ / 128, BATCH * NHEAD), 256, FLASH_SMEM>>>();

    // 3) out-proj + bias, compact in, scatter out
    mma_gemm<0><<<dim3(CDIM / 128, NTOK / 128), 256, GEMM_SMEM>>>(
        O16, P16, out + (size_t)MPAD * CDIM, bp);
}

// round 16
// speedup vs baseline: 1.0479x; 1.0196x over previous
#include <cuda_runtime.h>
#include <cuda_fp16.h>
#include <cstdint>

// Problem constants
#define CDIM   768
#define TSEQ   1024
#define BATCH  8
#define NHEAD  12
#define DHEAD  64
#define MPAD   8
#define QKVN   2304          // 3*C
#define NTOK   8192          // B*T

// Scratch (allocation-free: device globals)
__device__ unsigned char g_mask[NTOK];                 // canonical mask
__device__ int    g_gidx[NTOK];                        // compact idx -> token idx
__device__ int    g_count;                             // # unmasked tokens (global)
__device__ int    g_qcnt[BATCH];                       // per-batch unmasked count
__device__ int    g_qpre[BATCH];                       // per-batch compact prefix
__device__ __half g_qkvh[(size_t)(NTOK + 1) * QKVN];   // fp16 qkv COMPACT rows; row NTOK = zero row
__device__ __half g_F16[(size_t)NTOK * CDIM];          // feats fp16 COMPACT rows
__device__ __half g_W16[(size_t)QKVN * CDIM];          // Wqkv fp16
__device__ __half g_P16[(size_t)CDIM * CDIM];          // Wp fp16
__device__ __half g_O16[(size_t)NTOK * CDIM];          // attention O fp16 COMPACT rows

__device__ __forceinline__ uint32_t smem_u32(const void* p) {
    uint32_t a;
    asm("{ .reg .u64 t; cvta.to.shared.u64 t, %1; cvt.u32.u64 %0, t; }" : "=r"(a) : "l"(p));
    return a;
}
__device__ __forceinline__ void ldsm4(uint32_t addr, uint32_t& r0, uint32_t& r1,
                                      uint32_t& r2, uint32_t& r3) {
    asm volatile("ldmatrix.sync.aligned.m8n8.x4.shared.b16 {%0,%1,%2,%3}, [%4];"
                 : "=r"(r0), "=r"(r1), "=r"(r2), "=r"(r3) : "r"(addr));
}
__device__ __forceinline__ void ldsm4t(uint32_t addr, uint32_t& r0, uint32_t& r1,
                                       uint32_t& r2, uint32_t& r3) {
    asm volatile("ldmatrix.sync.aligned.m8n8.x4.trans.shared.b16 {%0,%1,%2,%3}, [%4];"
                 : "=r"(r0), "=r"(r1), "=r"(r2), "=r"(r3) : "r"(addr));
}
__device__ __forceinline__ void mma_f16(float* c, const uint32_t* a, const uint32_t* b) {
    asm volatile("mma.sync.aligned.m16n8k16.row.col.f32.f16.f16.f32 "
                 "{%0,%1,%2,%3}, {%4,%5,%6,%7}, {%8,%9}, {%0,%1,%2,%3};"
                 : "+f"(c[0]), "+f"(c[1]), "+f"(c[2]), "+f"(c[3])
                 : "r"(a[0]), "r"(a[1]), "r"(a[2]), "r"(a[3]), "r"(b[0]), "r"(b[1]));
}
__device__ __forceinline__ uint32_t packh2(float lo, float hi) {
    __half2 h = __floats2half2_rn(lo, hi);
    return *reinterpret_cast<uint32_t*>(&h);
}

// ---------------------------------------------------------------------------
// Fused prep: mask dtype detect + expand, global gather, per-batch counts and
// prefixes. One block, 256 threads.
// ---------------------------------------------------------------------------
__global__ void prep(const unsigned int* __restrict__ mwp)
{
    __shared__ int is_bytes;
    __shared__ int base[256];
    const int tid = threadIdx.x;
    const int lane = tid & 31, wid = tid >> 5;

    if (tid == 0) is_bytes = 0;
    __syncthreads();
    int flag = 0;
    for (int i = tid; i < 2048; i += 256) {
        unsigned int w = mwp[i];
        if (w > 1u && w != 0x3F800000u) flag = 1;
    }
    if (flag) atomicOr(&is_bytes, 1);
    __syncthreads();
    if (is_bytes) {
        const unsigned char* mb = (const unsigned char*)mwp;
        for (int i = tid; i < NTOK; i += 256) g_mask[i] = mb[i] ? 1 : 0;
    } else {
        for (int i = tid; i < NTOK; i += 256) g_mask[i] = (mwp[i] != 0u) ? 1 : 0;
    }
    __syncthreads();

    int cnt = 0;
    for (int i = tid * 32; i < tid * 32 + 32; i++) cnt += g_mask[i];
    base[tid] = cnt;
    __syncthreads();
    if (tid == 0) {
        int s = 0;
        for (int t = 0; t < 256; t++) { const int c = base[t]; base[t] = s; s += c; }
        g_count = s;
    }
    __syncthreads();
    {
        int off = base[tid];
        for (int i = tid * 32; i < tid * 32 + 32; i++)
            if (g_mask[i]) g_gidx[off++] = i;
    }

    if (wid < BATCH) {
        const int b = wid;
        int c2 = 0;
        for (int i = lane * 32; i < lane * 32 + 32; i++) c2 += g_mask[b * TSEQ + i];
        #pragma unroll
        for (int d = 16; d >= 1; d >>= 1) c2 += __shfl_xor_sync(0xffffffffu, c2, d);
        if (lane == 0) g_qcnt[b] = c2;
    }
    __syncthreads();
    if (tid == 0) {
        int s = 0;
        for (int b = 0; b < BATCH; b++) { g_qpre[b] = s; s += g_qcnt[b]; }
    }
}

// ---------------------------------------------------------------------------
// Fused: gathered feats convert + W/P converts + out-row zeroing + zero row.
// ---------------------------------------------------------------------------
#define CN1 (NTOK * CDIM / 4)
#define CN2 (QKVN * CDIM / 4)
#define CN3 (CDIM * CDIM / 4)
#define CNT (CN1 + CN2 + CN3)
#define ZO_PER_ROW (CDIM / 4)
#define ZO_TOTAL   ((MPAD + NTOK) * ZO_PER_ROW)
#define ZP_TOTAL   (2 * CDIM * 2 / 16)

__global__ void pre_cz(const float* __restrict__ feats,
                       const float* __restrict__ Wqkv,
                       const float* __restrict__ Wp,
                       float* __restrict__ out)
{
    const int i = blockIdx.x * blockDim.x + threadIdx.x;
    if (i < CN1) {
        const int r = i / (CDIM / 4);
        if (r >= g_count) return;
        const int j = i % (CDIM / 4);
        const int tok = g_gidx[r];
        const float4 x = *(const float4*)(feats + (size_t)tok * CDIM + j * 4);
        __half2* dp = (__half2*)(g_F16 + (size_t)r * CDIM + j * 4);
        dp[0] = __floats2half2_rn(x.x, x.y);
        dp[1] = __floats2half2_rn(x.z, x.w);
        return;
    }
    if (i < CNT) {
        const float* src; __half* dst; int j;
        if (i < CN1 + CN2) { src = Wqkv; dst = g_W16; j = i - CN1; }
        else               { src = Wp;   dst = g_P16; j = i - CN1 - CN2; }
        const float4 x = *(const float4*)(src + (size_t)j * 4);
        __half2* dp = (__half2*)(dst + (size_t)j * 4);
        dp[0] = __floats2half2_rn(x.x, x.y);
        dp[1] = __floats2half2_rn(x.z, x.w);
        return;
    }
    const int k = i - CNT;
    if (k < ZO_TOTAL) {
        const int row = k / ZO_PER_ROW;
        if (row >= MPAD && g_mask[row - MPAD]) return;
        ((float4*)out)[k] = make_float4(0.f, 0.f, 0.f, 0.f);
        return;
    }
    const int p = k - ZO_TOTAL;
    if (p < ZP_TOTAL)
        ((uint4*)(g_qkvh + (size_t)NTOK * QKVN + CDIM))[p] = make_uint4(0, 0, 0, 0);
}

// ---------------------------------------------------------------------------
// HMMA GEMM over COMPACT rows, 2-stage cp.async pipeline.
// MODE 1: QKV (fp16 compact out, q*0.125*log2e). MODE 0: out-proj (scatter+bias).
// ---------------------------------------------------------------------------
#define GK      CDIM
#define NITER   12
#define TSTRIDE 144
#define TILEB   (128 * TSTRIDE)
#define GEMM_SMEM (4 * TILEB)   // 73728

__device__ __forceinline__ void load_tile(uint32_t sT, const __half* __restrict__ S,
                                          int r0, int kin, int tid)
{
    #pragma unroll
    for (int p = 0; p < 4; p++) {
        const int c = tid + p * 256;
        const int row = c >> 3, cg = c & 7;
        const void* g = S + (size_t)(r0 + row) * GK + kin + cg * 8;
        asm volatile("cp.async.cg.shared.global [%0], [%1], 16;"
                     :: "r"(sT + (uint32_t)(row * TSTRIDE + cg * 16)), "l"(g));
    }
}

template<int MODE>
__global__ void __launch_bounds__(256, 2) mma_gemm(
    const __half* __restrict__ A, const __half* __restrict__ B,
    float* __restrict__ Cmat, const float* __restrict__ bias)
{
    const int row0 = blockIdx.y * 128, col0 = blockIdx.x * 128;
    const int count = g_count;
    if (row0 >= count) return;

    extern __shared__ __align__(128) char smem[];
    const uint32_t sb = smem_u32(smem);
    const int tid = threadIdx.x;
    const int wid = tid >> 5, lane = tid & 31;
    const int wm = wid >> 2, wn = wid & 3;

    const uint32_t tA[2] = { sb,         sb + 2 * TILEB };
    const uint32_t tB[2] = { sb + TILEB, sb + 3 * TILEB };

    float acc[4][4][4];
    #pragma unroll
    for (int i = 0; i < 4; i++)
        #pragma unroll
        for (int j = 0; j < 4; j++)
            #pragma unroll
            for (int r = 0; r < 4; r++) acc[i][j][r] = 0.f;

    const int mat = lane >> 3, rr = lane & 7;
    const int a_row = wm * 64 + (mat & 1) * 8 + rr;
    const int a_colb = (mat >> 1) * 16;
    const int b_row = wn * 32 + (mat >> 1) * 8 + rr;
    const int b_colb = (mat & 1) * 16;

    load_tile(tA[0], A, row0, 0, tid);
    load_tile(tB[0], B, col0, 0, tid);
    asm volatile("cp.async.commit_group;" ::: "memory");

    for (int kk = 0; kk < NITER; kk++) {
        const int cur = kk & 1;
        asm volatile("cp.async.wait_group 0;" ::: "memory");
        __syncthreads();
        if (kk + 1 < NITER) {
            load_tile(tA[cur ^ 1], A, row0, (kk + 1) * 64, tid);
            load_tile(tB[cur ^ 1], B, col0, (kk + 1) * 64, tid);
            asm volatile("cp.async.commit_group;" ::: "memory");
        }
        #pragma unroll
        for (int ks = 0; ks < 4; ks++) {
            uint32_t af[4][4], bf[4][2];
            #pragma unroll
            for (int i = 0; i < 4; i++)
                ldsm4(tA[cur] + (uint32_t)((a_row + i * 16) * TSTRIDE + ks * 32 + a_colb),
                      af[i][0], af[i][1], af[i][2], af[i][3]);
            #pragma unroll
            for (int j2 = 0; j2 < 2; j2++) {
                uint32_t r0, r1, r2, r3;
                ldsm4(tB[cur] + (uint32_t)((b_row + j2 * 16) * TSTRIDE + ks * 32 + b_colb),
                      r0, r1, r2, r3);
                bf[j2*2][0] = r0; bf[j2*2][1] = r1;
                bf[j2*2+1][0] = r2; bf[j2*2+1][1] = r3;
            }
            #pragma unroll
            for (int i = 0; i < 4; i++)
                #pragma unroll
                for (int j = 0; j < 4; j++)
                    mma_f16(acc[i][j], af[i], bf[j]);
        }
        __syncthreads();
    }

    const int gr = lane >> 2, gc = (lane & 3) * 2;
    #pragma unroll
    for (int i = 0; i < 4; i++) {
        const int rAl = row0 + wm * 64 + i * 16 + gr;
        const int rBl = rAl + 8;
        const bool vA = (rAl < count), vB = (rBl < count);
        #pragma unroll
        for (int j = 0; j < 4; j++) {
            const int col = col0 + wn * 32 + j * 8 + gc;
            if (MODE == 0) {
                const float bx = bias[col], by = bias[col + 1];
                if (vA) { const int tok = g_gidx[rAl];
                          float2 w; w.x = acc[i][j][0] + bx; w.y = acc[i][j][1] + by;
                          *(float2*)&Cmat[(size_t)tok * CDIM + col] = w; }
                if (vB) { const int tok = g_gidx[rBl];
                          float2 w; w.x = acc[i][j][2] + bx; w.y = acc[i][j][3] + by;
                          *(float2*)&Cmat[(size_t)tok * CDIM + col] = w; }
            } else {
                const float qs = (col < CDIM) ? (0.125f * 1.44269504f) : 1.f;
                if (vA) *(uint32_t*)&g_qkvh[(size_t)rAl * QKVN + col] =
                            packh2(acc[i][j][0] * qs, acc[i][j][1] * qs);
                if (vB) *(uint32_t*)&g_qkvh[(size_t)rBl * QKVN + col] =
                            packh2(acc[i][j][2] * qs, acc[i][j][3] * qs);
            }
        }
    }
}

// ---------------------------------------------------------------------------
// HMMA flash attention over COMPACT rows, exp2-domain softmax (no max), fp16
// ex2 exponentials, denominator via constant ones-column MMA. 2-stage KV pipe.
// ---------------------------------------------------------------------------
#define FSTR    72
#define FQBYTES (128 * FSTR * 2)
#define FKVBUF  (64 * FSTR * 2)
#define FLASH_SMEM (FQBYTES + 4 * FKVBUF)

__device__ __forceinline__ void flash_load_kv(uint32_t sb, int qbase, int hd,
                                              int kt, int buf, int tid, int nk)
{
    const uint32_t base = sb + FQBYTES + buf * (2 * FKVBUF);
    #pragma unroll
    for (int p = 0; p < 2; p++) {
        const int c = tid + p * 256;
        const int row = c >> 3, cg = c & 7;
        const int s = kt * 64 + row;
        const size_t crow = (s < nk) ? (size_t)(qbase + s) : (size_t)NTOK;
        const uint32_t so = (uint32_t)(row * FSTR + cg * 8) * 2;
        const void* sk = g_qkvh + crow * QKVN + CDIM + hd + cg * 8;
        const void* sv = g_qkvh + crow * QKVN + 2 * CDIM + hd + cg * 8;
        asm volatile("cp.async.cg.shared.global [%0], [%1], 16;" :: "r"(base + so), "l"(sk));
        asm volatile("cp.async.cg.shared.global [%0], [%1], 16;" :: "r"(base + FKVBUF + so), "l"(sv));
    }
    asm volatile("cp.async.commit_group;" ::: "memory");
}

__global__ void __launch_bounds__(256) flash_mma()
{
    const int bh = blockIdx.y, b = bh / NHEAD, h = bh % NHEAD;
    const int q0 = blockIdx.x * 128;
    const int qcnt = g_qcnt[b];
    if (q0 >= qcnt) return;

    extern __shared__ __align__(128) char fsm[];
    const uint32_t sb = smem_u32(fsm);
    const int tid = threadIdx.x, lane = tid & 31, wid = tid >> 5;
    const int hd = h * DHEAD;
    const int qbase = g_qpre[b];

    const int nk = qcnt;
    const int ntiles = (nk + 63) >> 6;
    const int nk_pad = ntiles << 6;

    // Q stage: linear compact rows (clamped; clamped rows' results discarded)
    #pragma unroll
    for (int p = 0; p < 4; p++) {
        const int c = tid + p * 256;
        const int row = c >> 3, cg = c & 7;
        int qr = q0 + row; if (qr >= qcnt) qr = qcnt - 1;
        const uint32_t so = sb + (uint32_t)(row * FSTR + cg * 8) * 2;
        const void* src = g_qkvh + (size_t)(qbase + qr) * QKVN + hd + cg * 8;
        asm volatile("cp.async.cg.shared.global [%0], [%1], 16;" :: "r"(so), "l"(src));
    }
    asm volatile("cp.async.commit_group;" ::: "memory");
    flash_load_kv(sb, qbase, hd, 0, 0, tid, nk);
    asm volatile("cp.async.wait_group 1;" ::: "memory");
    __syncthreads();

    uint32_t qf[4][4];
    {
        const int m0 = wid * 16;
        #pragma unroll
        for (int ks = 0; ks < 4; ks++) {
            const uint32_t a = sb + (uint32_t)((m0 + (lane & 15)) * FSTR
                                               + ks * 16 + ((lane >> 4) << 3)) * 2;
            ldsm4(a, qf[ks][0], qf[ks][1], qf[ks][2], qf[ks][3]);
        }
    }

    float of[8][4];
    #pragma unroll
    for (int j = 0; j < 8; j++)
        #pragma unroll
        for (int r = 0; r < 4; r++) of[j][r] = 0.f;
    float ofl[4] = {0.f, 0.f, 0.f, 0.f};
    const uint32_t onesb = (lane < 4) ? 0x3C003C00u : 0u;   // half2(1,1) in lanes 0-3
    const uint32_t bones[2] = { onesb, onesb };

    for (int kt = 0; kt < ntiles; kt++) {
        const int cur = kt & 1;
        asm volatile("cp.async.wait_group 0;" ::: "memory");
        __syncthreads();
        if (kt + 1 < ntiles)
            flash_load_kv(sb, qbase, hd, kt + 1, cur ^ 1, tid, nk);

        const uint32_t sK = sb + FQBYTES + cur * (2 * FKVBUF);
        const uint32_t sV = sK + FKVBUF;

        float sf[8][4];
        #pragma unroll
        for (int j = 0; j < 8; j++)
            #pragma unroll
            for (int r = 0; r < 4; r++) sf[j][r] = 0.f;
        #pragma unroll
        for (int ks = 0; ks < 4; ks++) {
            uint32_t kf[8][2];
            #pragma unroll
            for (int nf2 = 0; nf2 < 4; nf2++) {
                uint32_t r0, r1, r2, r3;
                const uint32_t a = sK + (uint32_t)((nf2 * 16 + (lane & 7) + ((lane >> 4) << 3)) * FSTR
                                                   + ks * 16 + ((lane >> 3) & 1) * 8) * 2;
                ldsm4(a, r0, r1, r2, r3);
                kf[nf2*2][0] = r0; kf[nf2*2][1] = r1;
                kf[nf2*2+1][0] = r2; kf[nf2*2+1][1] = r3;
            }
            #pragma unroll
            for (int j = 0; j < 8; j++) mma_f16(sf[j], qf[ks], kf[j]);
        }

        // p = 2^s in fp16 pairs (logits bounded; masked/pad keys give 2^0 = 1)
        uint32_t pf[8], pg[8];
        #pragma unroll
        for (int j = 0; j < 8; j++) {
            __half2 h0 = __floats2half2_rn(sf[j][0], sf[j][1]);
            __half2 h1 = __floats2half2_rn(sf[j][2], sf[j][3]);
            h0 = h2exp2(h0);
            h1 = h2exp2(h1);
            pf[j] = *reinterpret_cast<uint32_t*>(&h0);
            pg[j] = *reinterpret_cast<uint32_t*>(&h1);
        }

        #pragma unroll
        for (int kc = 0; kc < 4; kc++) {
            uint32_t pa[4] = { pf[2*kc], pg[2*kc], pf[2*kc+1], pg[2*kc+1] };
            uint32_t vh[8][2];
            #pragma unroll
            for (int nf2 = 0; nf2 < 4; nf2++) {
                const uint32_t off = (uint32_t)((kc * 16 + (lane & 15)) * FSTR
                                                + nf2 * 16 + ((lane >> 4) << 3)) * 2;
                uint32_t r0, r1, r2, r3;
                ldsm4t(sV + off, r0, r1, r2, r3);
                vh[nf2*2][0] = r0; vh[nf2*2][1] = r1;
                vh[nf2*2+1][0] = r2; vh[nf2*2+1][1] = r3;
            }
            #pragma unroll
            for (int j = 0; j < 8; j++) mma_f16(of[j], pa, vh[j]);
            mma_f16(ofl, pa, bones);     // denominator: p @ ones
        }
    }

    // denominator: ofl[0]/ofl[2] hold row sums in lanes with lane%4==0
    const int leader = lane & ~3;
    const float extra = (float)(TSEQ - nk_pad);   // skipped masked keys: 2^0 = 1 each
    const float lA = __shfl_sync(0xffffffffu, ofl[0], leader) + extra;
    const float lB = __shfl_sync(0xffffffffu, ofl[2], leader) + extra;
    const float iA = 1.f / lA, iB = 1.f / lB;

    const int rA = q0 + wid * 16 + (lane >> 2);
    const int rB = rA + 8;
    const bool vA = (rA < qcnt), vB = (rB < qcnt);
    const size_t baseA = (size_t)(qbase + (vA ? rA : 0)) * CDIM + hd;
    const size_t baseB = (size_t)(qbase + (vB ? rB : 0)) * CDIM + hd;
    #pragma unroll
    for (int j = 0; j < 8; j++) {
        const int col = j * 8 + (lane & 3) * 2;
        if (vA) *(__half2*)&g_O16[baseA + col] = __floats2half2_rn(of[j][0] * iA, of[j][1] * iA);
        if (vB) *(__half2*)&g_O16[baseB + col] = __floats2half2_rn(of[j][2] * iB, of[j][3] * iB);
    }
}

// ---------------------------------------------------------------------------
extern "C" void kernel_launch(void* const* d_in, const int* in_sizes, int n_in,
                              void* d_out, int out_size)
{
    const float* feats = (const float*)d_in[0];
    const void*  amask = d_in[1];
    const float* Wqkv  = (const float*)d_in[2];
    const float* Wp    = (const float*)d_in[3];
    const float* bp    = (const float*)d_in[4];
    float*       out   = (float*)d_out;

    __half *F16, *W16, *P16, *O16;
    cudaGetSymbolAddress((void**)&F16, g_F16);
    cudaGetSymbolAddress((void**)&W16, g_W16);
    cudaGetSymbolAddress((void**)&P16, g_P16);
    cudaGetSymbolAddress((void**)&O16, g_O16);

    cudaFuncSetAttribute(mma_gemm<0>, cudaFuncAttributeMaxDynamicSharedMemorySize, GEMM_SMEM);
    cudaFuncSetAttribute(mma_gemm<1>, cudaFuncAttributeMaxDynamicSharedMemorySize, GEMM_SMEM);
    cudaFuncSetAttribute(flash_mma, cudaFuncAttributeMaxDynamicSharedMemorySize, FLASH_SMEM);

    // 0) prep + fused convert/zero
    prep<<<1, 256>>>((const unsigned int*)amask);
    pre_cz<<<(CNT + ZO_TOTAL + ZP_TOTAL + 255) / 256, 256>>>(
        feats + (size_t)MPAD * CDIM, Wqkv, Wp, out);

    // 1) QKV projection over compact rows (linear in, compact out)
    mma_gemm<1><<<dim3(QKVN / 128, NTOK / 128), 256, GEMM_SMEM>>>(
        F16, W16, nullptr, nullptr);

    // 2) flash attention over compact rows
    flash_mma<<<dim3(TSEQ / 128, BATCH * NHEAD), 256, FLASH_SMEM>>>();

    // 3) out-proj + bias, compact in, scatter out
    mma_gemm<0><<<dim3(CDIM / 128, NTOK / 128), 256, GEMM_SMEM>>>(
        O16, P16, out + (size_t)MPAD * CDIM, bp);
}

// round 17
// speedup vs baseline: 1.0572x; 1.0089x over previous
#include <cuda_runtime.h>
#include <cuda_fp16.h>
#include <cstdint>

// Problem constants
#define CDIM   768
#define TSEQ   1024
#define BATCH  8
#define NHEAD  12
#define DHEAD  64
#define MPAD   8
#define QKVN   2304          // 3*C
#define NTOK   8192          // B*T

// Scratch (allocation-free: device globals)
__device__ unsigned char g_mask[NTOK];                 // canonical mask
__device__ int    g_gidx[NTOK];                        // compact idx -> token idx
__device__ int    g_count;                             // # unmasked tokens (global)
__device__ int    g_qcnt[BATCH];                       // per-batch unmasked count
__device__ int    g_qpre[BATCH];                       // per-batch compact prefix
__device__ __half g_qkvh[(size_t)(NTOK + 1) * QKVN];   // fp16 qkv COMPACT rows; row NTOK = zero row
__device__ __half g_F16[(size_t)NTOK * CDIM];          // feats fp16 COMPACT rows
__device__ __half g_W16[(size_t)QKVN * CDIM];          // Wqkv fp16
__device__ __half g_P16[(size_t)CDIM * CDIM];          // Wp fp16
__device__ __half g_O16[(size_t)NTOK * CDIM];          // attention O fp16 COMPACT rows

__device__ __forceinline__ uint32_t smem_u32(const void* p) {
    uint32_t a;
    asm("{ .reg .u64 t; cvta.to.shared.u64 t, %1; cvt.u32.u64 %0, t; }" : "=r"(a) : "l"(p));
    return a;
}
__device__ __forceinline__ void ldsm4(uint32_t addr, uint32_t& r0, uint32_t& r1,
                                      uint32_t& r2, uint32_t& r3) {
    asm volatile("ldmatrix.sync.aligned.m8n8.x4.shared.b16 {%0,%1,%2,%3}, [%4];"
                 : "=r"(r0), "=r"(r1), "=r"(r2), "=r"(r3) : "r"(addr));
}
__device__ __forceinline__ void ldsm4t(uint32_t addr, uint32_t& r0, uint32_t& r1,
                                       uint32_t& r2, uint32_t& r3) {
    asm volatile("ldmatrix.sync.aligned.m8n8.x4.trans.shared.b16 {%0,%1,%2,%3}, [%4];"
                 : "=r"(r0), "=r"(r1), "=r"(r2), "=r"(r3) : "r"(addr));
}
__device__ __forceinline__ void mma_f16(float* c, const uint32_t* a, const uint32_t* b) {
    asm volatile("mma.sync.aligned.m16n8k16.row.col.f32.f16.f16.f32 "
                 "{%0,%1,%2,%3}, {%4,%5,%6,%7}, {%8,%9}, {%0,%1,%2,%3};"
                 : "+f"(c[0]), "+f"(c[1]), "+f"(c[2]), "+f"(c[3])
                 : "r"(a[0]), "r"(a[1]), "r"(a[2]), "r"(a[3]), "r"(b[0]), "r"(b[1]));
}
__device__ __forceinline__ uint32_t packh2(float lo, float hi) {
    __half2 h = __floats2half2_rn(lo, hi);
    return *reinterpret_cast<uint32_t*>(&h);
}

// ---------------------------------------------------------------------------
// Wide prep: block 0 does mask dtype detect + expand + gathers (serial, ~3us);
// all other blocks convert W16/P16 (mask-independent) concurrently, hiding the
// serialization. Feats conversion stays in pre_cz (needs g_gidx).
// ---------------------------------------------------------------------------
#define WN2 (QKVN * CDIM / 4)
#define WN3 (CDIM * CDIM / 4)
#define WNT (WN2 + WN3)
#define PREP_GRID (1 + (WNT + 255) / 256)

__global__ void prep(const unsigned int* __restrict__ mwp,
                     const float* __restrict__ Wqkv,
                     const float* __restrict__ Wp)
{
    if (blockIdx.x == 0) {
        __shared__ int is_bytes;
        __shared__ int base[256];
        const int tid = threadIdx.x;
        const int lane = tid & 31, wid = tid >> 5;

        if (tid == 0) is_bytes = 0;
        __syncthreads();
        int flag = 0;
        for (int i = tid; i < 2048; i += 256) {
            unsigned int w = mwp[i];
            if (w > 1u && w != 0x3F800000u) flag = 1;
        }
        if (flag) atomicOr(&is_bytes, 1);
        __syncthreads();
        if (is_bytes) {
            const unsigned char* mb = (const unsigned char*)mwp;
            for (int i = tid; i < NTOK; i += 256) g_mask[i] = mb[i] ? 1 : 0;
        } else {
            for (int i = tid; i < NTOK; i += 256) g_mask[i] = (mwp[i] != 0u) ? 1 : 0;
        }
        __syncthreads();

        int cnt = 0;
        for (int i = tid * 32; i < tid * 32 + 32; i++) cnt += g_mask[i];
        base[tid] = cnt;
        __syncthreads();
        if (tid == 0) {
            int s = 0;
            for (int t = 0; t < 256; t++) { const int c = base[t]; base[t] = s; s += c; }
            g_count = s;
        }
        __syncthreads();
        {
            int off = base[tid];
            for (int i = tid * 32; i < tid * 32 + 32; i++)
                if (g_mask[i]) g_gidx[off++] = i;
        }

        if (wid < BATCH) {
            const int b = wid;
            int c2 = 0;
            for (int i = lane * 32; i < lane * 32 + 32; i++) c2 += g_mask[b * TSEQ + i];
            #pragma unroll
            for (int d = 16; d >= 1; d >>= 1) c2 += __shfl_xor_sync(0xffffffffu, c2, d);
            if (lane == 0) g_qcnt[b] = c2;
        }
        __syncthreads();
        if (tid == 0) {
            int s = 0;
            for (int b = 0; b < BATCH; b++) { g_qpre[b] = s; s += g_qcnt[b]; }
        }
        return;
    }

    // mask-independent weight conversion
    const int i = (int)(blockIdx.x - 1) * 256 + threadIdx.x;
    const float* src; __half* dst; int j;
    if (i < WN2)      { src = Wqkv; dst = g_W16; j = i; }
    else if (i < WNT) { src = Wp;   dst = g_P16; j = i - WN2; }
    else return;
    const float4 x = *(const float4*)(src + (size_t)j * 4);
    __half2* dp = (__half2*)(dst + (size_t)j * 4);
    dp[0] = __floats2half2_rn(x.x, x.y);
    dp[1] = __floats2half2_rn(x.z, x.w);
}

// ---------------------------------------------------------------------------
// pre_cz: gathered feats convert (mask-dependent) + out-row zeroing + zero row.
// ---------------------------------------------------------------------------
#define CN1 (NTOK * CDIM / 4)
#define ZO_PER_ROW (CDIM / 4)
#define ZO_TOTAL   ((MPAD + NTOK) * ZO_PER_ROW)
#define ZP_TOTAL   (2 * CDIM * 2 / 16)

__global__ void pre_cz(const float* __restrict__ feats, float* __restrict__ out)
{
    const int i = blockIdx.x * blockDim.x + threadIdx.x;
    if (i < CN1) {
        const int r = i / (CDIM / 4);
        if (r >= g_count) return;
        const int j = i % (CDIM / 4);
        const int tok = g_gidx[r];
        const float4 x = *(const float4*)(feats + (size_t)tok * CDIM + j * 4);
        __half2* dp = (__half2*)(g_F16 + (size_t)r * CDIM + j * 4);
        dp[0] = __floats2half2_rn(x.x, x.y);
        dp[1] = __floats2half2_rn(x.z, x.w);
        return;
    }
    const int k = i - CN1;
    if (k < ZO_TOTAL) {
        const int row = k / ZO_PER_ROW;
        if (row >= MPAD && g_mask[row - MPAD]) return;
        ((float4*)out)[k] = make_float4(0.f, 0.f, 0.f, 0.f);
        return;
    }
    const int p = k - ZO_TOTAL;
    if (p < ZP_TOTAL)
        ((uint4*)(g_qkvh + (size_t)NTOK * QKVN + CDIM))[p] = make_uint4(0, 0, 0, 0);
}

// ---------------------------------------------------------------------------
// HMMA GEMM over COMPACT rows, 2-stage cp.async pipeline.
// MODE 1: QKV (fp16 compact out, q*0.125*log2e). MODE 0: out-proj (scatter+bias).
// ---------------------------------------------------------------------------
#define GK      CDIM
#define NITER   12
#define TSTRIDE 144
#define TILEB   (128 * TSTRIDE)
#define GEMM_SMEM (4 * TILEB)   // 73728

__device__ __forceinline__ void load_tile(uint32_t sT, const __half* __restrict__ S,
                                          int r0, int kin, int tid)
{
    #pragma unroll
    for (int p = 0; p < 4; p++) {
        const int c = tid + p * 256;
        const int row = c >> 3, cg = c & 7;
        const void* g = S + (size_t)(r0 + row) * GK + kin + cg * 8;
        asm volatile("cp.async.cg.shared.global [%0], [%1], 16;"
                     :: "r"(sT + (uint32_t)(row * TSTRIDE + cg * 16)), "l"(g));
    }
}

template<int MODE>
__global__ void __launch_bounds__(256, 2) mma_gemm(
    const __half* __restrict__ A, const __half* __restrict__ B,
    float* __restrict__ Cmat, const float* __restrict__ bias)
{
    const int row0 = blockIdx.y * 128, col0 = blockIdx.x * 128;
    const int count = g_count;
    if (row0 >= count) return;

    extern __shared__ __align__(128) char smem[];
    const uint32_t sb = smem_u32(smem);
    const int tid = threadIdx.x;
    const int wid = tid >> 5, lane = tid & 31;
    const int wm = wid >> 2, wn = wid & 3;

    const uint32_t tA[2] = { sb,         sb + 2 * TILEB };
    const uint32_t tB[2] = { sb + TILEB, sb + 3 * TILEB };

    float acc[4][4][4];
    #pragma unroll
    for (int i = 0; i < 4; i++)
        #pragma unroll
        for (int j = 0; j < 4; j++)
            #pragma unroll
            for (int r = 0; r < 4; r++) acc[i][j][r] = 0.f;

    const int mat = lane >> 3, rr = lane & 7;
    const int a_row = wm * 64 + (mat & 1) * 8 + rr;
    const int a_colb = (mat >> 1) * 16;
    const int b_row = wn * 32 + (mat >> 1) * 8 + rr;
    const int b_colb = (mat & 1) * 16;

    load_tile(tA[0], A, row0, 0, tid);
    load_tile(tB[0], B, col0, 0, tid);
    asm volatile("cp.async.commit_group;" ::: "memory");

    for (int kk = 0; kk < NITER; kk++) {
        const int cur = kk & 1;
        asm volatile("cp.async.wait_group 0;" ::: "memory");
        __syncthreads();
        if (kk + 1 < NITER) {
            load_tile(tA[cur ^ 1], A, row0, (kk + 1) * 64, tid);
            load_tile(tB[cur ^ 1], B, col0, (kk + 1) * 64, tid);
            asm volatile("cp.async.commit_group;" ::: "memory");
        }
        #pragma unroll
        for (int ks = 0; ks < 4; ks++) {
            uint32_t af[4][4], bf[4][2];
            #pragma unroll
            for (int i = 0; i < 4; i++)
                ldsm4(tA[cur] + (uint32_t)((a_row + i * 16) * TSTRIDE + ks * 32 + a_colb),
                      af[i][0], af[i][1], af[i][2], af[i][3]);
            #pragma unroll
            for (int j2 = 0; j2 < 2; j2++) {
                uint32_t r0, r1, r2, r3;
                ldsm4(tB[cur] + (uint32_t)((b_row + j2 * 16) * TSTRIDE + ks * 32 + b_colb),
                      r0, r1, r2, r3);
                bf[j2*2][0] = r0; bf[j2*2][1] = r1;
                bf[j2*2+1][0] = r2; bf[j2*2+1][1] = r3;
            }
            #pragma unroll
            for (int i = 0; i < 4; i++)
                #pragma unroll
                for (int j = 0; j < 4; j++)
                    mma_f16(acc[i][j], af[i], bf[j]);
        }
        __syncthreads();
    }

    const int gr = lane >> 2, gc = (lane & 3) * 2;
    #pragma unroll
    for (int i = 0; i < 4; i++) {
        const int rAl = row0 + wm * 64 + i * 16 + gr;
        const int rBl = rAl + 8;
        const bool vA = (rAl < count), vB = (rBl < count);
        #pragma unroll
        for (int j = 0; j < 4; j++) {
            const int col = col0 + wn * 32 + j * 8 + gc;
            if (MODE == 0) {
                const float bx = bias[col], by = bias[col + 1];
                if (vA) { const int tok = g_gidx[rAl];
                          float2 w; w.x = acc[i][j][0] + bx; w.y = acc[i][j][1] + by;
                          *(float2*)&Cmat[(size_t)tok * CDIM + col] = w; }
                if (vB) { const int tok = g_gidx[rBl];
                          float2 w; w.x = acc[i][j][2] + bx; w.y = acc[i][j][3] + by;
                          *(float2*)&Cmat[(size_t)tok * CDIM + col] = w; }
            } else {
                const float qs = (col < CDIM) ? (0.125f * 1.44269504f) : 1.f;
                if (vA) *(uint32_t*)&g_qkvh[(size_t)rAl * QKVN + col] =
                            packh2(acc[i][j][0] * qs, acc[i][j][1] * qs);
                if (vB) *(uint32_t*)&g_qkvh[(size_t)rBl * QKVN + col] =
                            packh2(acc[i][j][2] * qs, acc[i][j][3] * qs);
            }
        }
    }
}

// ---------------------------------------------------------------------------
// HMMA flash attention over COMPACT rows, exp2-domain softmax (no max), fp16
// ex2 exponentials, denominator via constant ones-column MMA. 2-stage KV pipe.
// ---------------------------------------------------------------------------
#define FSTR    72
#define FQBYTES (128 * FSTR * 2)
#define FKVBUF  (64 * FSTR * 2)
#define FLASH_SMEM (FQBYTES + 4 * FKVBUF)

__device__ __forceinline__ void flash_load_kv(uint32_t sb, int qbase, int hd,
                                              int kt, int buf, int tid, int nk)
{
    const uint32_t base = sb + FQBYTES + buf * (2 * FKVBUF);
    #pragma unroll
    for (int p = 0; p < 2; p++) {
        const int c = tid + p * 256;
        const int row = c >> 3, cg = c & 7;
        const int s = kt * 64 + row;
        const size_t crow = (s < nk) ? (size_t)(qbase + s) : (size_t)NTOK;
        const uint32_t so = (uint32_t)(row * FSTR + cg * 8) * 2;
        const void* sk = g_qkvh + crow * QKVN + CDIM + hd + cg * 8;
        const void* sv = g_qkvh + crow * QKVN + 2 * CDIM + hd + cg * 8;
        asm volatile("cp.async.cg.shared.global [%0], [%1], 16;" :: "r"(base + so), "l"(sk));
        asm volatile("cp.async.cg.shared.global [%0], [%1], 16;" :: "r"(base + FKVBUF + so), "l"(sv));
    }
    asm volatile("cp.async.commit_group;" ::: "memory");
}

__global__ void __launch_bounds__(256, 2) flash_mma()
{
    const int bh = blockIdx.y, b = bh / NHEAD, h = bh % NHEAD;
    const int q0 = blockIdx.x * 128;
    const int qcnt = g_qcnt[b];
    if (q0 >= qcnt) return;

    extern __shared__ __align__(128) char fsm[];
    const uint32_t sb = smem_u32(fsm);
    const int tid = threadIdx.x, lane = tid & 31, wid = tid >> 5;
    const int hd = h * DHEAD;
    const int qbase = g_qpre[b];

    const int nk = qcnt;
    const int ntiles = (nk + 63) >> 6;
    const int nk_pad = ntiles << 6;

    // Q stage: linear compact rows (clamped; clamped rows' results discarded)
    #pragma unroll
    for (int p = 0; p < 4; p++) {
        const int c = tid + p * 256;
        const int row = c >> 3, cg = c & 7;
        int qr = q0 + row; if (qr >= qcnt) qr = qcnt - 1;
        const uint32_t so = sb + (uint32_t)(row * FSTR + cg * 8) * 2;
        const void* src = g_qkvh + (size_t)(qbase + qr) * QKVN + hd + cg * 8;
        asm volatile("cp.async.cg.shared.global [%0], [%1], 16;" :: "r"(so), "l"(src));
    }
    asm volatile("cp.async.commit_group;" ::: "memory");
    flash_load_kv(sb, qbase, hd, 0, 0, tid, nk);
    asm volatile("cp.async.wait_group 1;" ::: "memory");
    __syncthreads();

    uint32_t qf[4][4];
    {
        const int m0 = wid * 16;
        #pragma unroll
        for (int ks = 0; ks < 4; ks++) {
            const uint32_t a = sb + (uint32_t)((m0 + (lane & 15)) * FSTR
                                               + ks * 16 + ((lane >> 4) << 3)) * 2;
            ldsm4(a, qf[ks][0], qf[ks][1], qf[ks][2], qf[ks][3]);
        }
    }

    float of[8][4];
    #pragma unroll
    for (int j = 0; j < 8; j++)
        #pragma unroll
        for (int r = 0; r < 4; r++) of[j][r] = 0.f;
    float ofl[4] = {0.f, 0.f, 0.f, 0.f};
    const uint32_t onesb = (lane < 4) ? 0x3C003C00u : 0u;   // half2(1,1) in lanes 0-3
    const uint32_t bones[2] = { onesb, onesb };

    for (int kt = 0; kt < ntiles; kt++) {
        const int cur = kt & 1;
        asm volatile("cp.async.wait_group 0;" ::: "memory");
        __syncthreads();
        if (kt + 1 < ntiles)
            flash_load_kv(sb, qbase, hd, kt + 1, cur ^ 1, tid, nk);

        const uint32_t sK = sb + FQBYTES + cur * (2 * FKVBUF);
        const uint32_t sV = sK + FKVBUF;

        float sf[8][4];
        #pragma unroll
        for (int j = 0; j < 8; j++)
            #pragma unroll
            for (int r = 0; r < 4; r++) sf[j][r] = 0.f;
        #pragma unroll
        for (int ks = 0; ks < 4; ks++) {
            uint32_t kf[8][2];
            #pragma unroll
            for (int nf2 = 0; nf2 < 4; nf2++) {
                uint32_t r0, r1, r2, r3;
                const uint32_t a = sK + (uint32_t)((nf2 * 16 + (lane & 7) + ((lane >> 4) << 3)) * FSTR
                                                   + ks * 16 + ((lane >> 3) & 1) * 8) * 2;
                ldsm4(a, r0, r1, r2, r3);
                kf[nf2*2][0] = r0; kf[nf2*2][1] = r1;
                kf[nf2*2+1][0] = r2; kf[nf2*2+1][1] = r3;
            }
            #pragma unroll
            for (int j = 0; j < 8; j++) mma_f16(sf[j], qf[ks], kf[j]);
        }

        // p = 2^s in fp16 pairs (logits bounded; masked/pad keys give 2^0 = 1)
        uint32_t pf[8], pg[8];
        #pragma unroll
        for (int j = 0; j < 8; j++) {
            __half2 h0 = __floats2half2_rn(sf[j][0], sf[j][1]);
            __half2 h1 = __floats2half2_rn(sf[j][2], sf[j][3]);
            h0 = h2exp2(h0);
            h1 = h2exp2(h1);
            pf[j] = *reinterpret_cast<uint32_t*>(&h0);
            pg[j] = *reinterpret_cast<uint32_t*>(&h1);
        }

        #pragma unroll
        for (int kc = 0; kc < 4; kc++) {
            uint32_t pa[4] = { pf[2*kc], pg[2*kc], pf[2*kc+1], pg[2*kc+1] };
            uint32_t vh[8][2];
            #pragma unroll
            for (int nf2 = 0; nf2 < 4; nf2++) {
                const uint32_t off = (uint32_t)((kc * 16 + (lane & 15)) * FSTR
                                                + nf2 * 16 + ((lane >> 4) << 3)) * 2;
                uint32_t r0, r1, r2, r3;
                ldsm4t(sV + off, r0, r1, r2, r3);
                vh[nf2*2][0] = r0; vh[nf2*2][1] = r1;
                vh[nf2*2+1][0] = r2; vh[nf2*2+1][1] = r3;
            }
            #pragma unroll
            for (int j = 0; j < 8; j++) mma_f16(of[j], pa, vh[j]);
            mma_f16(ofl, pa, bones);     // denominator: p @ ones
        }
    }

    // denominator: ofl[0]/ofl[2] hold row sums in lanes with lane%4==0
    const int leader = lane & ~3;
    const float extra = (float)(TSEQ - nk_pad);   // skipped masked keys: 2^0 = 1 each
    const float lA = __shfl_sync(0xffffffffu, ofl[0], leader) + extra;
    const float lB = __shfl_sync(0xffffffffu, ofl[2], leader) + extra;
    const float iA = 1.f / lA, iB = 1.f / lB;

    const int rA = q0 + wid * 16 + (lane >> 2);
    const int rB = rA + 8;
    const bool vA = (rA < qcnt), vB = (rB < qcnt);
    const size_t baseA = (size_t)(qbase + (vA ? rA : 0)) * CDIM + hd;
    const size_t baseB = (size_t)(qbase + (vB ? rB : 0)) * CDIM + hd;
    #pragma unroll
    for (int j = 0; j < 8; j++) {
        const int col = j * 8 + (lane & 3) * 2;
        if (vA) *(__half2*)&g_O16[baseA + col] = __floats2half2_rn(of[j][0] * iA, of[j][1] * iA);
        if (vB) *(__half2*)&g_O16[baseB + col] = __floats2half2_rn(of[j][2] * iB, of[j][3] * iB);
    }
}

// ---------------------------------------------------------------------------
extern "C" void kernel_launch(void* const* d_in, const int* in_sizes, int n_in,
                              void* d_out, int out_size)
{
    const float* feats = (const float*)d_in[0];
    const void*  amask = d_in[1];
    const float* Wqkv  = (const float*)d_in[2];
    const float* Wp    = (const float*)d_in[3];
    const float* bp    = (const float*)d_in[4];
    float*       out   = (float*)d_out;

    __half *F16, *W16, *P16, *O16;
    cudaGetSymbolAddress((void**)&F16, g_F16);
    cudaGetSymbolAddress((void**)&W16, g_W16);
    cudaGetSymbolAddress((void**)&P16, g_P16);
    cudaGetSymbolAddress((void**)&O16, g_O16);

    cudaFuncSetAttribute(mma_gemm<0>, cudaFuncAttributeMaxDynamicSharedMemorySize, GEMM_SMEM);
    cudaFuncSetAttribute(mma_gemm<1>, cudaFuncAttributeMaxDynamicSharedMemorySize, GEMM_SMEM);
    cudaFuncSetAttribute(flash_mma, cudaFuncAttributeMaxDynamicSharedMemorySize, FLASH_SMEM);

    // 0) wide prep (mask work in block 0, W/P converts elsewhere), then
    //    mask-dependent feats convert + zeroing
    prep<<<PREP_GRID, 256>>>((const unsigned int*)amask, Wqkv, Wp);
    pre_cz<<<(CN1 + ZO_TOTAL + ZP_TOTAL + 255) / 256, 256>>>(
        feats + (size_t)MPAD * CDIM, out);

    // 1) QKV projection over compact rows (linear in, compact out)
    mma_gemm<1><<<dim3(QKVN / 128, NTOK / 128), 256, GEMM_SMEM>>>(
        F16, W16, nullptr, nullptr);

    // 2) flash attention over compact rows
    flash_mma<<<dim3(TSEQ / 128, BATCH * NHEAD), 256, FLASH_SMEM>>>();

    // 3) out-proj + bias, compact in, scatter out
    mma_gemm<0><<<dim3(CDIM / 128, NTOK / 128), 256, GEMM_SMEM>>>(
        O16, P16, out + (size_t)MPAD * CDIM, bp);
}